// round 1
// baseline (speedup 1.0000x reference)
#include <cuda_runtime.h>

#define NN 100000
#define MM 12
#define FF 128
#define NFF 64

// ---------------- scratch (static device globals: no allocation) ----------
__device__ float g_q[(size_t)NN * FF];
__device__ float g_k[(size_t)NN * FF];
__device__ float g_v[(size_t)NN * FF];
__device__ int   g_is64;

// ---------------- index dtype detection ------------------------------------
// If nbr_fea_idx is int64 (little-endian), every high 32-bit word of the
// first 64 values is 0 (values < 1e5). If int32, those words are random
// indices in [0,1e5) -> probability all-zero ~ 0.
__global__ void detect_idx_kernel(const unsigned int* __restrict__ p) {
    int is64 = 1;
    for (int k = 0; k < 64; k++) {
        if (p[2 * k + 1] != 0u) { is64 = 0; break; }
    }
    g_is64 = is64;
}

// ---------------- Kernel A: fused QKV projection ---------------------------
// grid = N/32 blocks, 256 threads. Each block: 32 rows. Weights staged in
// smem one at a time (q,k,v). Thread = (col quad jq in [0,32), row group rg
// in [0,8)) computing a 4x4 register tile. Activations in smem with stride
// 33 (conflict-free scalar broadcast reads).
#define A_ROWS 32
#define A_SMEM_FLOATS (16384 + 128 * 33)
#define A_SMEM_BYTES  (A_SMEM_FLOATS * 4)

__global__ __launch_bounds__(256, 2) void qkv_kernel(
    const float* __restrict__ atom,
    const float* __restrict__ Wq, const float* __restrict__ bq,
    const float* __restrict__ Wk, const float* __restrict__ bk,
    const float* __restrict__ Wv, const float* __restrict__ bv)
{
    extern __shared__ float sm[];
    float* sW = sm;            // 128*128
    float* aS = sm + 16384;    // 128 * 33 (i-major, row minor, pad 33)

    const int tid  = threadIdx.x;
    const int row0 = blockIdx.x * A_ROWS;

    // load 32 activation rows, transposed into aS[i*33 + r]
    for (int e = tid; e < A_ROWS * FF; e += 256) {
        int r = e >> 7;
        int i = e & 127;
        aS[i * 33 + r] = atom[(size_t)(row0 + r) * FF + i];
    }

    const int jq = tid & 31;   // column quad -> cols 4*jq..4*jq+3
    const int rg = tid >> 5;   // row group  -> rows 4*rg..4*rg+3

    const float* Ws[3]  = {Wq, Wk, Wv};
    const float* bsx[3] = {bq, bk, bv};
    float* os[3];
    os[0] = g_q; os[1] = g_k; os[2] = g_v;

#pragma unroll
    for (int w = 0; w < 3; w++) {
        __syncthreads();   // protect sW reuse (and aS before first compute)
        {
            const float4* src = (const float4*)Ws[w];
            float4* dst = (float4*)sW;
            for (int e = tid; e < (FF * FF) / 4; e += 256) dst[e] = src[e];
        }
        __syncthreads();

        float acc[4][4];
#pragma unroll
        for (int r = 0; r < 4; r++)
#pragma unroll
            for (int c = 0; c < 4; c++) acc[r][c] = 0.f;

#pragma unroll 2
        for (int i = 0; i < FF; i++) {
            const float4 w4 = *(const float4*)&sW[i * FF + (jq << 2)];
            const float a0 = aS[i * 33 + (rg << 2) + 0];
            const float a1 = aS[i * 33 + (rg << 2) + 1];
            const float a2 = aS[i * 33 + (rg << 2) + 2];
            const float a3 = aS[i * 33 + (rg << 2) + 3];
            acc[0][0] = fmaf(a0, w4.x, acc[0][0]);
            acc[0][1] = fmaf(a0, w4.y, acc[0][1]);
            acc[0][2] = fmaf(a0, w4.z, acc[0][2]);
            acc[0][3] = fmaf(a0, w4.w, acc[0][3]);
            acc[1][0] = fmaf(a1, w4.x, acc[1][0]);
            acc[1][1] = fmaf(a1, w4.y, acc[1][1]);
            acc[1][2] = fmaf(a1, w4.z, acc[1][2]);
            acc[1][3] = fmaf(a1, w4.w, acc[1][3]);
            acc[2][0] = fmaf(a2, w4.x, acc[2][0]);
            acc[2][1] = fmaf(a2, w4.y, acc[2][1]);
            acc[2][2] = fmaf(a2, w4.z, acc[2][2]);
            acc[2][3] = fmaf(a2, w4.w, acc[2][3]);
            acc[3][0] = fmaf(a3, w4.x, acc[3][0]);
            acc[3][1] = fmaf(a3, w4.y, acc[3][1]);
            acc[3][2] = fmaf(a3, w4.z, acc[3][2]);
            acc[3][3] = fmaf(a3, w4.w, acc[3][3]);
        }

        const float4 b4 = *(const float4*)&bsx[w][jq << 2];
        float* outp = os[w];
#pragma unroll
        for (int r = 0; r < 4; r++) {
            float4 o4;
            o4.x = acc[r][0] + b4.x;
            o4.y = acc[r][1] + b4.y;
            o4.z = acc[r][2] + b4.z;
            o4.w = acc[r][3] + b4.w;
            *(float4*)&outp[(size_t)(row0 + (rg << 2) + r) * FF + (jq << 2)] = o4;
        }
    }
}

// ---------------- Kernel B: fused attention + gate + LayerNorm -------------
// 256 threads = 2 groups of 128; each group processes one node per
// iteration; persistent grid-stride over node pairs. Thread j owns feature
// j (head h=j/16, dim d=j%16).
#define OFF_WN  0          /* 64*128  = 8192  */
#define OFF_WO  8192       /* 128*128 = 16384 */
#define OFF_WG  24576      /* 256             */
#define OFF_BN  24832      /* 128             */
#define OFF_BO  24960      /* 128             */
#define OFF_GA  25088      /* 128             */
#define OFF_BE  25216      /* 128             */
#define OFF_NBR 25344      /* 2*768 = 1536    */
#define OFF_ATT 26880      /* 2*128 = 256     */
#define OFF_RED 27136      /* 2*4             */
#define OFF_R1  27144      /* 2*4             */
#define OFF_R2  27152      /* 2*4             */
#define OFF_IDX 27160      /* 2*12 ints       */
#define B_SMEM_FLOATS 27184
#define B_SMEM_BYTES  (B_SMEM_FLOATS * 4)

__global__ __launch_bounds__(256, 2) void attn_kernel(
    const float* __restrict__ atom, const float* __restrict__ nbr,
    const void*  __restrict__ idxp,
    const float* __restrict__ Wn, const float* __restrict__ bn,
    const float* __restrict__ Wo, const float* __restrict__ bo,
    const float* __restrict__ Wg, const float* __restrict__ bg,
    const float* __restrict__ gamma, const float* __restrict__ beta,
    float* __restrict__ outp)
{
    extern __shared__ float sm[];
    float* sWn = sm + OFF_WN;
    float* sWo = sm + OFF_WO;
    float* sWg = sm + OFF_WG;
    int*   idxS = (int*)(sm + OFF_IDX);

    const int tid = threadIdx.x;
    const int g   = tid >> 7;     // group 0/1
    const int j   = tid & 127;    // feature index

    // one-time weight staging
    for (int e = tid; e < NFF * FF; e += 256) sWn[e] = Wn[e];
    for (int e = tid; e < FF * FF; e += 256)  sWo[e] = Wo[e];
    if (tid < 2 * FF) sWg[tid] = Wg[tid];
    if (tid < FF) {
        sm[OFF_BN + tid] = bn[tid];
        sm[OFF_BO + tid] = bo[tid];
        sm[OFF_GA + tid] = gamma[tid];
        sm[OFF_BE + tid] = beta[tid];
    }
    const int is64 = g_is64;
    __syncthreads();

    const float bnj = sm[OFF_BN + j];
    const float boj = sm[OFF_BO + j];
    const float gaj = sm[OFF_GA + j];
    const float bej = sm[OFF_BE + j];
    const float wgo = sWg[j];
    const float wgr = sWg[FF + j];
    const float bgv = __ldg(bg);

    const int lane = j & 31;
    const int wrp  = j >> 5;   // warp index within group (0..3)

    float* nb   = sm + OFF_NBR + g * (MM * NFF);
    float* attp = sm + OFF_ATT + g * FF;

    const int npairs = NN / 2;
    for (int pair = blockIdx.x; pair < npairs; pair += gridDim.x) {
        const int n = pair * 2 + g;

        __syncthreads();   // guard smem reuse from previous iteration

        // stage neighbor features transposed: nb[i*12 + m]
        {
            const float* nf = nbr + (size_t)n * (MM * NFF);
            for (int e = j; e < MM * NFF; e += 128) {
                const int m = e >> 6;
                const int i = e & 63;
                nb[i * MM + m] = nf[e];
            }
        }
        if (j < MM) {
            int ix;
            if (is64) ix = (int)((const long long*)idxp)[(size_t)n * MM + j];
            else      ix = ((const int*)idxp)[(size_t)n * MM + j];
            idxS[g * MM + j] = ix;
        }
        __syncthreads();

        // nbr_t[m][j] = bn[j] + sum_i nbr[m][i] * Wn[i][j]
        float t[MM];
#pragma unroll
        for (int m = 0; m < MM; m++) t[m] = bnj;
#pragma unroll 4
        for (int i = 0; i < NFF; i++) {
            const float w  = sWn[i * FF + j];
            const float4 a0 = *(const float4*)&nb[i * MM + 0];
            const float4 a1 = *(const float4*)&nb[i * MM + 4];
            const float4 a2 = *(const float4*)&nb[i * MM + 8];
            t[0]  = fmaf(a0.x, w, t[0]);
            t[1]  = fmaf(a0.y, w, t[1]);
            t[2]  = fmaf(a0.z, w, t[2]);
            t[3]  = fmaf(a0.w, w, t[3]);
            t[4]  = fmaf(a1.x, w, t[4]);
            t[5]  = fmaf(a1.y, w, t[5]);
            t[6]  = fmaf(a1.z, w, t[6]);
            t[7]  = fmaf(a1.w, w, t[7]);
            t[8]  = fmaf(a2.x, w, t[8]);
            t[9]  = fmaf(a2.y, w, t[9]);
            t[10] = fmaf(a2.z, w, t[10]);
            t[11] = fmaf(a2.w, w, t[11]);
        }

        // gather k/v, combine, per-head score partials
        const float qj = g_q[(size_t)n * FF + j];
        float nv[MM], sc[MM];
#pragma unroll
        for (int m = 0; m < MM; m++) {
            const int ix = idxS[g * MM + m];
            const float kk = g_k[(size_t)ix * FF + j];
            const float vv = g_v[(size_t)ix * FF + j];
            const float nk = kk + t[m];
            nv[m] = vv + t[m];
            sc[m] = qj * nk;
        }
        // reduce over 16 lanes of the head
#pragma unroll
        for (int m = 0; m < MM; m++) {
            sc[m] += __shfl_xor_sync(0xffffffffu, sc[m], 8);
            sc[m] += __shfl_xor_sync(0xffffffffu, sc[m], 4);
            sc[m] += __shfl_xor_sync(0xffffffffu, sc[m], 2);
            sc[m] += __shfl_xor_sync(0xffffffffu, sc[m], 1);
        }
        // softmax over M (replicated across head lanes), scale 1/sqrt(16)
        float mx = -1e30f;
#pragma unroll
        for (int m = 0; m < MM; m++) { sc[m] *= 0.25f; mx = fmaxf(mx, sc[m]); }
        float se = 0.f;
#pragma unroll
        for (int m = 0; m < MM; m++) { sc[m] = __expf(sc[m] - mx); se += sc[m]; }
        const float inv = 1.f / se;
        float att = 0.f;
#pragma unroll
        for (int m = 0; m < MM; m++) att = fmaf(sc[m] * inv, nv[m], att);

        attp[j] = att;
        __syncthreads();

        // out = att @ Wo + bo
        float o = boj;
#pragma unroll 4
        for (int i = 0; i < FF; i += 4) {
            const float4 a4 = *(const float4*)&attp[i];
            o = fmaf(a4.x, sWo[(i + 0) * FF + j], o);
            o = fmaf(a4.y, sWo[(i + 1) * FF + j], o);
            o = fmaf(a4.z, sWo[(i + 2) * FF + j], o);
            o = fmaf(a4.w, sWo[(i + 3) * FF + j], o);
        }

        // gate = sigmoid([out,res] @ Wg + bg)
        const float resj = atom[(size_t)n * FF + j];
        float gp = o * wgo + resj * wgr;
#pragma unroll
        for (int off = 16; off >= 1; off >>= 1)
            gp += __shfl_xor_sync(0xffffffffu, gp, off);
        if (lane == 0) sm[OFF_RED + g * 4 + wrp] = gp;
        __syncthreads();
        const float z = sm[OFF_RED + g * 4 + 0] + sm[OFF_RED + g * 4 + 1] +
                        sm[OFF_RED + g * 4 + 2] + sm[OFF_RED + g * 4 + 3] + bgv;
        const float gate = 1.f / (1.f + __expf(-z));
        const float y = gate * o + (1.f - gate) * resj;

        // LayerNorm over 128 features
        float s1 = y, s2 = y * y;
#pragma unroll
        for (int off = 16; off >= 1; off >>= 1) {
            s1 += __shfl_xor_sync(0xffffffffu, s1, off);
            s2 += __shfl_xor_sync(0xffffffffu, s2, off);
        }
        if (lane == 0) {
            sm[OFF_R1 + g * 4 + wrp] = s1;
            sm[OFF_R2 + g * 4 + wrp] = s2;
        }
        __syncthreads();
        const float mu  = (sm[OFF_R1 + g * 4 + 0] + sm[OFF_R1 + g * 4 + 1] +
                           sm[OFF_R1 + g * 4 + 2] + sm[OFF_R1 + g * 4 + 3]) * (1.f / FF);
        const float ex2 = (sm[OFF_R2 + g * 4 + 0] + sm[OFF_R2 + g * 4 + 1] +
                           sm[OFF_R2 + g * 4 + 2] + sm[OFF_R2 + g * 4 + 3]) * (1.f / FF);
        const float var = ex2 - mu * mu;
        const float yn  = (y - mu) * rsqrtf(var + 1e-5f) * gaj + bej;

        outp[(size_t)n * FF + j] = yn;
    }
}

// ---------------- launch ----------------------------------------------------
extern "C" void kernel_launch(void* const* d_in, const int* in_sizes, int n_in,
                              void* d_out, int out_size)
{
    const float* atom = (const float*)d_in[0];
    const float* nbrf = (const float*)d_in[1];
    const void*  idx  = d_in[2];
    const float* Wq = (const float*)d_in[3];
    const float* bq = (const float*)d_in[4];
    const float* Wk = (const float*)d_in[5];
    const float* bk = (const float*)d_in[6];
    const float* Wv = (const float*)d_in[7];
    const float* bv = (const float*)d_in[8];
    const float* Wn = (const float*)d_in[9];
    const float* bn = (const float*)d_in[10];
    const float* Wo = (const float*)d_in[11];
    const float* bo = (const float*)d_in[12];
    const float* Wg = (const float*)d_in[13];
    const float* bg = (const float*)d_in[14];
    const float* ga = (const float*)d_in[15];
    const float* be = (const float*)d_in[16];
    float* out = (float*)d_out;

    cudaFuncSetAttribute(qkv_kernel,  cudaFuncAttributeMaxDynamicSharedMemorySize, A_SMEM_BYTES);
    cudaFuncSetAttribute(attn_kernel, cudaFuncAttributeMaxDynamicSharedMemorySize, B_SMEM_BYTES);

    detect_idx_kernel<<<1, 1>>>((const unsigned int*)idx);
    qkv_kernel<<<NN / A_ROWS, 256, A_SMEM_BYTES>>>(atom, Wq, bq, Wk, bk, Wv, bv);
    attn_kernel<<<296, 256, B_SMEM_BYTES>>>(atom, nbrf, idx,
                                            Wn, bn, Wo, bo, Wg, bg, ga, be, out);
}

// round 2
// speedup vs baseline: 2.3036x; 2.3036x over previous
#include <cuda_runtime.h>

#define NN 100000
#define MM 12
#define FF 128
#define NFF 64

// ---------------- static device scratch (no allocations) -------------------
__device__ float g_q[(size_t)NN * FF];
__device__ float g_k[(size_t)NN * FF];
__device__ float g_v[(size_t)NN * FF];
__device__ float g_t[(size_t)NN * MM * FF];   // neighbor transform, per edge
__device__ float g_att[(size_t)NN * FF];
__device__ int   g_is64;

// ---------------- helpers ---------------------------------------------------
__device__ __forceinline__ unsigned f2tf(float x) {
    unsigned u;
    asm("cvt.rna.tf32.f32 %0, %1;" : "=r"(u) : "f"(x));
    return u;
}

// D += A(16x8,row) @ B(8x8,col) in tf32, fp32 accumulate
__device__ __forceinline__ void mma8(float* d, const unsigned* a,
                                     unsigned b0, unsigned b1) {
    asm volatile(
        "mma.sync.aligned.m16n8k8.row.col.f32.tf32.tf32.f32 "
        "{%0,%1,%2,%3}, {%4,%5,%6,%7}, {%8,%9}, {%0,%1,%2,%3};"
        : "+f"(d[0]), "+f"(d[1]), "+f"(d[2]), "+f"(d[3])
        : "r"(a[0]), "r"(a[1]), "r"(a[2]), "r"(a[3]), "r"(b0), "r"(b1));
}

// ---------------- index dtype detection ------------------------------------
__global__ void detect_idx_kernel(const unsigned int* __restrict__ p) {
    int is64 = 1;
    for (int k = 0; k < 64; k++) {
        if (p[2 * k + 1] != 0u) { is64 = 0; break; }
    }
    g_is64 = is64;
}

// ---------------- GEMM tiling constants ------------------------------------
// block tile 64 rows x 128 cols, 8 warps in 2x4 grid; each warp 32x32.
// smem pads: LD mod 32 == 4 makes fragment loads conflict-free (4g+t unique).
#define LDA 132
#define LDW 132
#define LDA2 68

#define QKV_SMEM ((64 * LDA + 128 * LDW) * 4)
#define NBR_SMEM ((64 * LDA2 + 64 * LDW) * 4)
#define OUT_SMEM ((64 * LDA + 128 * LDW) * 4 + 64 * 4 * 3 * 4)

// ---------------- Kernel 1: QKV projections (tf32 MMA) ---------------------
__global__ __launch_bounds__(256, 2) void gemm_qkv(
    const float* __restrict__ atom,
    const float* __restrict__ Wq, const float* __restrict__ bq,
    const float* __restrict__ Wk, const float* __restrict__ bk,
    const float* __restrict__ Wv, const float* __restrict__ bv)
{
    extern __shared__ unsigned sh[];
    unsigned* sA = sh;
    unsigned* sW = sh + 64 * LDA;

    const int tid  = threadIdx.x;
    const int row0 = blockIdx.x * 64;
    const int w    = blockIdx.y;
    const float* W    = (w == 0) ? Wq : (w == 1) ? Wk : Wv;
    const float* bias = (w == 0) ? bq : (w == 1) ? bk : bv;
    float* out        = (w == 0) ? g_q : (w == 1) ? g_k : g_v;

    // stage A (64x128) with row guard, vectorized
    for (int e = tid; e < 64 * 32; e += 256) {
        int r = e >> 5, c4 = e & 31;
        int row = row0 + r;
        float4 v = (row < NN) ? *(const float4*)&atom[(size_t)row * FF + c4 * 4]
                              : make_float4(0.f, 0.f, 0.f, 0.f);
        sA[r * LDA + c4 * 4 + 0] = f2tf(v.x);
        sA[r * LDA + c4 * 4 + 1] = f2tf(v.y);
        sA[r * LDA + c4 * 4 + 2] = f2tf(v.z);
        sA[r * LDA + c4 * 4 + 3] = f2tf(v.w);
    }
    // stage W (128x128)
    for (int e = tid; e < 128 * 32; e += 256) {
        int r = e >> 5, c4 = e & 31;
        float4 v = *(const float4*)&W[r * FF + c4 * 4];
        sW[r * LDW + c4 * 4 + 0] = f2tf(v.x);
        sW[r * LDW + c4 * 4 + 1] = f2tf(v.y);
        sW[r * LDW + c4 * 4 + 2] = f2tf(v.z);
        sW[r * LDW + c4 * 4 + 3] = f2tf(v.w);
    }
    __syncthreads();

    const int lane = tid & 31, g = lane >> 2, t = lane & 3;
    const int warp = tid >> 5, wr = warp >> 2, wc = warp & 3;
    const int Rb = wr * 32, Cb = wc * 32;

    float acc[2][4][4];
#pragma unroll
    for (int mt = 0; mt < 2; mt++)
#pragma unroll
        for (int nt = 0; nt < 4; nt++)
#pragma unroll
            for (int f = 0; f < 4; f++) acc[mt][nt][f] = 0.f;

#pragma unroll
    for (int k0 = 0; k0 < 128; k0 += 8) {
        unsigned a[2][4];
#pragma unroll
        for (int mt = 0; mt < 2; mt++) {
            int r = Rb + mt * 16 + g;
            a[mt][0] = sA[r * LDA + k0 + t];
            a[mt][1] = sA[(r + 8) * LDA + k0 + t];
            a[mt][2] = sA[r * LDA + k0 + t + 4];
            a[mt][3] = sA[(r + 8) * LDA + k0 + t + 4];
        }
#pragma unroll
        for (int nt = 0; nt < 4; nt++) {
            unsigned b0 = sW[(k0 + t) * LDW + Cb + nt * 8 + g];
            unsigned b1 = sW[(k0 + t + 4) * LDW + Cb + nt * 8 + g];
            mma8(acc[0][nt], a[0], b0, b1);
            mma8(acc[1][nt], a[1], b0, b1);
        }
    }

#pragma unroll
    for (int nt = 0; nt < 4; nt++) {
        int c0 = Cb + nt * 8 + 2 * t;
        float2 b2 = __ldg((const float2*)&bias[c0]);
#pragma unroll
        for (int mt = 0; mt < 2; mt++) {
            int r1 = row0 + Rb + mt * 16 + g;
            int r2 = r1 + 8;
            if (r1 < NN) {
                float2 o = make_float2(acc[mt][nt][0] + b2.x, acc[mt][nt][1] + b2.y);
                *(float2*)&out[(size_t)r1 * FF + c0] = o;
            }
            if (r2 < NN) {
                float2 o = make_float2(acc[mt][nt][2] + b2.x, acc[mt][nt][3] + b2.y);
                *(float2*)&out[(size_t)r2 * FF + c0] = o;
            }
        }
    }
}

// ---------------- Kernel 2: neighbor transform (tf32 MMA, K=64) ------------
__global__ __launch_bounds__(256, 3) void gemm_nbr(
    const float* __restrict__ nbr,
    const float* __restrict__ Wn, const float* __restrict__ bn)
{
    extern __shared__ unsigned sh[];
    unsigned* sA = sh;
    unsigned* sW = sh + 64 * LDA2;

    const int tid = threadIdx.x;
    const size_t row0 = (size_t)blockIdx.x * 64;   // edge rows; exact multiple

    for (int e = tid; e < 64 * 16; e += 256) {
        int r = e >> 4, c4 = e & 15;
        float4 v = *(const float4*)&nbr[(row0 + r) * NFF + c4 * 4];
        sA[r * LDA2 + c4 * 4 + 0] = f2tf(v.x);
        sA[r * LDA2 + c4 * 4 + 1] = f2tf(v.y);
        sA[r * LDA2 + c4 * 4 + 2] = f2tf(v.z);
        sA[r * LDA2 + c4 * 4 + 3] = f2tf(v.w);
    }
    for (int e = tid; e < 64 * 32; e += 256) {
        int r = e >> 5, c4 = e & 31;
        float4 v = *(const float4*)&Wn[r * FF + c4 * 4];
        sW[r * LDW + c4 * 4 + 0] = f2tf(v.x);
        sW[r * LDW + c4 * 4 + 1] = f2tf(v.y);
        sW[r * LDW + c4 * 4 + 2] = f2tf(v.z);
        sW[r * LDW + c4 * 4 + 3] = f2tf(v.w);
    }
    __syncthreads();

    const int lane = tid & 31, g = lane >> 2, t = lane & 3;
    const int warp = tid >> 5, wr = warp >> 2, wc = warp & 3;
    const int Rb = wr * 32, Cb = wc * 32;

    float acc[2][4][4];
#pragma unroll
    for (int mt = 0; mt < 2; mt++)
#pragma unroll
        for (int nt = 0; nt < 4; nt++)
#pragma unroll
            for (int f = 0; f < 4; f++) acc[mt][nt][f] = 0.f;

#pragma unroll
    for (int k0 = 0; k0 < 64; k0 += 8) {
        unsigned a[2][4];
#pragma unroll
        for (int mt = 0; mt < 2; mt++) {
            int r = Rb + mt * 16 + g;
            a[mt][0] = sA[r * LDA2 + k0 + t];
            a[mt][1] = sA[(r + 8) * LDA2 + k0 + t];
            a[mt][2] = sA[r * LDA2 + k0 + t + 4];
            a[mt][3] = sA[(r + 8) * LDA2 + k0 + t + 4];
        }
#pragma unroll
        for (int nt = 0; nt < 4; nt++) {
            unsigned b0 = sW[(k0 + t) * LDW + Cb + nt * 8 + g];
            unsigned b1 = sW[(k0 + t + 4) * LDW + Cb + nt * 8 + g];
            mma8(acc[0][nt], a[0], b0, b1);
            mma8(acc[1][nt], a[1], b0, b1);
        }
    }

#pragma unroll
    for (int nt = 0; nt < 4; nt++) {
        int c0 = Cb + nt * 8 + 2 * t;
        float2 b2 = __ldg((const float2*)&bn[c0]);
#pragma unroll
        for (int mt = 0; mt < 2; mt++) {
            size_t r1 = row0 + Rb + mt * 16 + g;
            float2 o1 = make_float2(acc[mt][nt][0] + b2.x, acc[mt][nt][1] + b2.y);
            float2 o2 = make_float2(acc[mt][nt][2] + b2.x, acc[mt][nt][3] + b2.y);
            *(float2*)&g_t[r1 * FF + c0] = o1;
            *(float2*)&g_t[(r1 + 8) * FF + c0] = o2;
        }
    }
}

// ---------------- Kernel 3: attention core (no smem, no sync) --------------
// 256 threads = 2 nodes; thread j owns feature j (head = j/16).
__global__ __launch_bounds__(256) void attn_core(const void* __restrict__ idxp)
{
    const int tid = threadIdx.x;
    const int j = tid & 127;
    const int n = blockIdx.x * 2 + (tid >> 7);

    const float qj = g_q[(size_t)n * FF + j];

    int ixs[MM];
    if (g_is64) {
        const long long* ip = (const long long*)idxp;
#pragma unroll
        for (int m = 0; m < MM; m++) ixs[m] = (int)__ldg(&ip[(size_t)n * MM + m]);
    } else {
        const int* ip = (const int*)idxp;
#pragma unroll
        for (int m = 0; m < MM; m++) ixs[m] = __ldg(&ip[(size_t)n * MM + m]);
    }

    float tt[MM], nv[MM], sc[MM];
#pragma unroll
    for (int m = 0; m < MM; m++) tt[m] = g_t[((size_t)n * MM + m) * FF + j];
#pragma unroll
    for (int m = 0; m < MM; m++) {
        const float kk = g_k[(size_t)ixs[m] * FF + j];
        const float vv = g_v[(size_t)ixs[m] * FF + j];
        sc[m] = qj * (kk + tt[m]);
        nv[m] = vv + tt[m];
    }
    // reduce over 16 lanes of the head
#pragma unroll
    for (int m = 0; m < MM; m++) {
        sc[m] += __shfl_xor_sync(0xffffffffu, sc[m], 8);
        sc[m] += __shfl_xor_sync(0xffffffffu, sc[m], 4);
        sc[m] += __shfl_xor_sync(0xffffffffu, sc[m], 2);
        sc[m] += __shfl_xor_sync(0xffffffffu, sc[m], 1);
    }
    float mx = -1e30f;
#pragma unroll
    for (int m = 0; m < MM; m++) { sc[m] *= 0.25f; mx = fmaxf(mx, sc[m]); }
    float se = 0.f;
#pragma unroll
    for (int m = 0; m < MM; m++) { sc[m] = __expf(sc[m] - mx); se += sc[m]; }
    const float inv = 1.f / se;
    float att = 0.f;
#pragma unroll
    for (int m = 0; m < MM; m++) att = fmaf(sc[m] * inv, nv[m], att);

    g_att[(size_t)n * FF + j] = att;
}

// ---------------- Kernel 4: out GEMM + gate + LayerNorm (fused) ------------
__global__ __launch_bounds__(256, 2) void gemm_out(
    const float* __restrict__ atom,
    const float* __restrict__ Wo, const float* __restrict__ bo,
    const float* __restrict__ Wg, const float* __restrict__ bg,
    const float* __restrict__ gamma, const float* __restrict__ beta,
    float* __restrict__ outp)
{
    extern __shared__ unsigned sh[];
    unsigned* sA = sh;
    unsigned* sW = sh + 64 * LDA;
    float* zred = (float*)(sh + 64 * LDA + 128 * LDW);   // [64][4]
    float* s1r  = zred + 256;                             // [64][4]
    float* s2r  = s1r + 256;                              // [64][4]

    const int tid  = threadIdx.x;
    const int row0 = blockIdx.x * 64;

    for (int e = tid; e < 64 * 32; e += 256) {
        int r = e >> 5, c4 = e & 31;
        int row = row0 + r;
        float4 v = (row < NN) ? *(const float4*)&g_att[(size_t)row * FF + c4 * 4]
                              : make_float4(0.f, 0.f, 0.f, 0.f);
        sA[r * LDA + c4 * 4 + 0] = f2tf(v.x);
        sA[r * LDA + c4 * 4 + 1] = f2tf(v.y);
        sA[r * LDA + c4 * 4 + 2] = f2tf(v.z);
        sA[r * LDA + c4 * 4 + 3] = f2tf(v.w);
    }
    for (int e = tid; e < 128 * 32; e += 256) {
        int r = e >> 5, c4 = e & 31;
        float4 v = *(const float4*)&Wo[r * FF + c4 * 4];
        sW[r * LDW + c4 * 4 + 0] = f2tf(v.x);
        sW[r * LDW + c4 * 4 + 1] = f2tf(v.y);
        sW[r * LDW + c4 * 4 + 2] = f2tf(v.z);
        sW[r * LDW + c4 * 4 + 3] = f2tf(v.w);
    }
    __syncthreads();

    const int lane = tid & 31, g = lane >> 2, t = lane & 3;
    const int warp = tid >> 5, wr = warp >> 2, wc = warp & 3;
    const int Rb = wr * 32, Cb = wc * 32;

    float acc[2][4][4];
#pragma unroll
    for (int mt = 0; mt < 2; mt++)
#pragma unroll
        for (int nt = 0; nt < 4; nt++)
#pragma unroll
            for (int f = 0; f < 4; f++) acc[mt][nt][f] = 0.f;

#pragma unroll
    for (int k0 = 0; k0 < 128; k0 += 8) {
        unsigned a[2][4];
#pragma unroll
        for (int mt = 0; mt < 2; mt++) {
            int r = Rb + mt * 16 + g;
            a[mt][0] = sA[r * LDA + k0 + t];
            a[mt][1] = sA[(r + 8) * LDA + k0 + t];
            a[mt][2] = sA[r * LDA + k0 + t + 4];
            a[mt][3] = sA[(r + 8) * LDA + k0 + t + 4];
        }
#pragma unroll
        for (int nt = 0; nt < 4; nt++) {
            unsigned b0 = sW[(k0 + t) * LDW + Cb + nt * 8 + g];
            unsigned b1 = sW[(k0 + t + 4) * LDW + Cb + nt * 8 + g];
            mma8(acc[0][nt], a[0], b0, b1);
            mma8(acc[1][nt], a[1], b0, b1);
        }
    }

    // epilogue: bias, residual, gate partials
    float res[2][4][4];
    float gp[2][2] = {{0.f, 0.f}, {0.f, 0.f}};
#pragma unroll
    for (int nt = 0; nt < 4; nt++) {
        int c0 = Cb + nt * 8 + 2 * t;
        float2 b2  = __ldg((const float2*)&bo[c0]);
        float2 wo2 = __ldg((const float2*)&Wg[c0]);
        float2 wr2 = __ldg((const float2*)&Wg[FF + c0]);
#pragma unroll
        for (int mt = 0; mt < 2; mt++) {
            int r1 = row0 + Rb + mt * 16 + g;
            int r2 = r1 + 8;
            float2 rA = (r1 < NN) ? *(const float2*)&atom[(size_t)r1 * FF + c0]
                                  : make_float2(0.f, 0.f);
            float2 rB = (r2 < NN) ? *(const float2*)&atom[(size_t)r2 * FF + c0]
                                  : make_float2(0.f, 0.f);
            acc[mt][nt][0] += b2.x; acc[mt][nt][1] += b2.y;
            acc[mt][nt][2] += b2.x; acc[mt][nt][3] += b2.y;
            res[mt][nt][0] = rA.x;  res[mt][nt][1] = rA.y;
            res[mt][nt][2] = rB.x;  res[mt][nt][3] = rB.y;
            gp[mt][0] += acc[mt][nt][0] * wo2.x + acc[mt][nt][1] * wo2.y
                       + rA.x * wr2.x + rA.y * wr2.y;
            gp[mt][1] += acc[mt][nt][2] * wo2.x + acc[mt][nt][3] * wo2.y
                       + rB.x * wr2.x + rB.y * wr2.y;
        }
    }
    // quad reduction (lanes with same g differ only in t = low 2 bits)
#pragma unroll
    for (int mt = 0; mt < 2; mt++) {
#pragma unroll
        for (int h = 0; h < 2; h++) {
            gp[mt][h] += __shfl_xor_sync(0xffffffffu, gp[mt][h], 1);
            gp[mt][h] += __shfl_xor_sync(0xffffffffu, gp[mt][h], 2);
        }
    }
    if (t == 0) {
#pragma unroll
        for (int mt = 0; mt < 2; mt++)
#pragma unroll
            for (int h = 0; h < 2; h++)
                zred[(Rb + mt * 16 + g + h * 8) * 4 + wc] = gp[mt][h];
    }
    __syncthreads();

    const float bgv = __ldg(bg);
    float gate[2][2];
#pragma unroll
    for (int mt = 0; mt < 2; mt++)
#pragma unroll
        for (int h = 0; h < 2; h++) {
            int rl = Rb + mt * 16 + g + h * 8;
            float z = zred[rl * 4 + 0] + zred[rl * 4 + 1] +
                      zred[rl * 4 + 2] + zred[rl * 4 + 3] + bgv;
            gate[mt][h] = 1.f / (1.f + __expf(-z));
        }

    // gated output + LN sum partials
    float s1[2][2] = {{0.f, 0.f}, {0.f, 0.f}};
    float s2[2][2] = {{0.f, 0.f}, {0.f, 0.f}};
#pragma unroll
    for (int mt = 0; mt < 2; mt++)
#pragma unroll
        for (int nt = 0; nt < 4; nt++)
#pragma unroll
            for (int f = 0; f < 4; f++) {
                int h = f >> 1;
                float y = gate[mt][h] * acc[mt][nt][f]
                        + (1.f - gate[mt][h]) * res[mt][nt][f];
                res[mt][nt][f] = y;
                s1[mt][h] += y;
                s2[mt][h] += y * y;
            }
#pragma unroll
    for (int mt = 0; mt < 2; mt++)
#pragma unroll
        for (int h = 0; h < 2; h++) {
            s1[mt][h] += __shfl_xor_sync(0xffffffffu, s1[mt][h], 1);
            s1[mt][h] += __shfl_xor_sync(0xffffffffu, s1[mt][h], 2);
            s2[mt][h] += __shfl_xor_sync(0xffffffffu, s2[mt][h], 1);
            s2[mt][h] += __shfl_xor_sync(0xffffffffu, s2[mt][h], 2);
        }
    if (t == 0) {
#pragma unroll
        for (int mt = 0; mt < 2; mt++)
#pragma unroll
            for (int h = 0; h < 2; h++) {
                int rl = Rb + mt * 16 + g + h * 8;
                s1r[rl * 4 + wc] = s1[mt][h];
                s2r[rl * 4 + wc] = s2[mt][h];
            }
    }
    __syncthreads();

    float mu[2][2], rs[2][2];
#pragma unroll
    for (int mt = 0; mt < 2; mt++)
#pragma unroll
        for (int h = 0; h < 2; h++) {
            int rl = Rb + mt * 16 + g + h * 8;
            float m1 = (s1r[rl * 4 + 0] + s1r[rl * 4 + 1] +
                        s1r[rl * 4 + 2] + s1r[rl * 4 + 3]) * (1.f / FF);
            float m2 = (s2r[rl * 4 + 0] + s2r[rl * 4 + 1] +
                        s2r[rl * 4 + 2] + s2r[rl * 4 + 3]) * (1.f / FF);
            mu[mt][h] = m1;
            rs[mt][h] = rsqrtf(m2 - m1 * m1 + 1e-5f);
        }

#pragma unroll
    for (int nt = 0; nt < 4; nt++) {
        int c0 = Cb + nt * 8 + 2 * t;
        float2 ga2 = __ldg((const float2*)&gamma[c0]);
        float2 be2 = __ldg((const float2*)&beta[c0]);
#pragma unroll
        for (int mt = 0; mt < 2; mt++) {
            int r1 = row0 + Rb + mt * 16 + g;
            int r2 = r1 + 8;
            if (r1 < NN) {
                float2 o;
                o.x = (res[mt][nt][0] - mu[mt][0]) * rs[mt][0] * ga2.x + be2.x;
                o.y = (res[mt][nt][1] - mu[mt][0]) * rs[mt][0] * ga2.y + be2.y;
                *(float2*)&outp[(size_t)r1 * FF + c0] = o;
            }
            if (r2 < NN) {
                float2 o;
                o.x = (res[mt][nt][2] - mu[mt][1]) * rs[mt][1] * ga2.x + be2.x;
                o.y = (res[mt][nt][3] - mu[mt][1]) * rs[mt][1] * ga2.y + be2.y;
                *(float2*)&outp[(size_t)r2 * FF + c0] = o;
            }
        }
    }
}

// ---------------- launch ----------------------------------------------------
extern "C" void kernel_launch(void* const* d_in, const int* in_sizes, int n_in,
                              void* d_out, int out_size)
{
    const float* atom = (const float*)d_in[0];
    const float* nbrf = (const float*)d_in[1];
    const void*  idx  = d_in[2];
    const float* Wq = (const float*)d_in[3];
    const float* bq = (const float*)d_in[4];
    const float* Wk = (const float*)d_in[5];
    const float* bk = (const float*)d_in[6];
    const float* Wv = (const float*)d_in[7];
    const float* bv = (const float*)d_in[8];
    const float* Wn = (const float*)d_in[9];
    const float* bn = (const float*)d_in[10];
    const float* Wo = (const float*)d_in[11];
    const float* bo = (const float*)d_in[12];
    const float* Wg = (const float*)d_in[13];
    const float* bg = (const float*)d_in[14];
    const float* ga = (const float*)d_in[15];
    const float* be = (const float*)d_in[16];
    float* out = (float*)d_out;

    cudaFuncSetAttribute(gemm_qkv, cudaFuncAttributeMaxDynamicSharedMemorySize, QKV_SMEM);
    cudaFuncSetAttribute(gemm_nbr, cudaFuncAttributeMaxDynamicSharedMemorySize, NBR_SMEM);
    cudaFuncSetAttribute(gemm_out, cudaFuncAttributeMaxDynamicSharedMemorySize, OUT_SMEM);

    detect_idx_kernel<<<1, 1>>>((const unsigned int*)idx);
    gemm_qkv<<<dim3((NN + 63) / 64, 3), 256, QKV_SMEM>>>(atom, Wq, bq, Wk, bk, Wv, bv);
    gemm_nbr<<<(NN * MM) / 64, 256, NBR_SMEM>>>(nbrf, Wn, bn);
    attn_core<<<NN / 2, 256>>>(idx);
    gemm_out<<<(NN + 63) / 64, 256, OUT_SMEM>>>(atom, Wo, bo, Wg, bg, ga, be, out);
}

// round 3
// speedup vs baseline: 3.0423x; 1.3206x over previous
#include <cuda_runtime.h>

#define NN 100000
#define MM 12
#define FF 128
#define NFF 64

// ---------------- static device scratch (no allocations) -------------------
__device__ float g_q[(size_t)NN * FF];
__device__ float g_k[(size_t)NN * FF];
__device__ float g_v[(size_t)NN * FF];
__device__ float g_att[(size_t)NN * FF];
__device__ int   g_is64;

// ---------------- helpers ---------------------------------------------------
__device__ __forceinline__ unsigned f2tf(float x) {
    unsigned u;
    asm("cvt.rna.tf32.f32 %0, %1;" : "=r"(u) : "f"(x));
    return u;
}

__device__ __forceinline__ void mma8(float* d, const unsigned* a,
                                     unsigned b0, unsigned b1) {
    asm volatile(
        "mma.sync.aligned.m16n8k8.row.col.f32.tf32.tf32.f32 "
        "{%0,%1,%2,%3}, {%4,%5,%6,%7}, {%8,%9}, {%0,%1,%2,%3};"
        : "+f"(d[0]), "+f"(d[1]), "+f"(d[2]), "+f"(d[3])
        : "r"(a[0]), "r"(a[1]), "r"(a[2]), "r"(a[3]), "r"(b0), "r"(b1));
}

// ---------------- index dtype detection ------------------------------------
__global__ void detect_idx_kernel(const unsigned int* __restrict__ p) {
    int is64 = 1;
    for (int k = 0; k < 64; k++) {
        if (p[2 * k + 1] != 0u) { is64 = 0; break; }
    }
    g_is64 = is64;
}

// ---------------- GEMM tiling constants ------------------------------------
#define LDA 132
#define LDW 132
#define LDA2 68

#define QKV_SMEM ((64 * LDA + 128 * LDW) * 4)
#define OUT_SMEM ((64 * LDA + 128 * LDW) * 4 + 64 * 4 * 3 * 4)

// ---------------- Kernel 1: QKV projections (tf32 MMA) ---------------------
__global__ __launch_bounds__(256, 2) void gemm_qkv(
    const float* __restrict__ atom,
    const float* __restrict__ Wq, const float* __restrict__ bq,
    const float* __restrict__ Wk, const float* __restrict__ bk,
    const float* __restrict__ Wv, const float* __restrict__ bv)
{
    extern __shared__ unsigned sh[];
    unsigned* sA = sh;
    unsigned* sW = sh + 64 * LDA;

    const int tid  = threadIdx.x;
    const int row0 = blockIdx.x * 64;
    const int w    = blockIdx.y;
    const float* W    = (w == 0) ? Wq : (w == 1) ? Wk : Wv;
    const float* bias = (w == 0) ? bq : (w == 1) ? bk : bv;
    float* out        = (w == 0) ? g_q : (w == 1) ? g_k : g_v;

    for (int e = tid; e < 64 * 32; e += 256) {
        int r = e >> 5, c4 = e & 31;
        int row = row0 + r;
        float4 v = (row < NN) ? *(const float4*)&atom[(size_t)row * FF + c4 * 4]
                              : make_float4(0.f, 0.f, 0.f, 0.f);
        sA[r * LDA + c4 * 4 + 0] = f2tf(v.x);
        sA[r * LDA + c4 * 4 + 1] = f2tf(v.y);
        sA[r * LDA + c4 * 4 + 2] = f2tf(v.z);
        sA[r * LDA + c4 * 4 + 3] = f2tf(v.w);
    }
    for (int e = tid; e < 128 * 32; e += 256) {
        int r = e >> 5, c4 = e & 31;
        float4 v = *(const float4*)&W[r * FF + c4 * 4];
        sW[r * LDW + c4 * 4 + 0] = f2tf(v.x);
        sW[r * LDW + c4 * 4 + 1] = f2tf(v.y);
        sW[r * LDW + c4 * 4 + 2] = f2tf(v.z);
        sW[r * LDW + c4 * 4 + 3] = f2tf(v.w);
    }
    __syncthreads();

    const int lane = tid & 31, g = lane >> 2, t = lane & 3;
    const int warp = tid >> 5, wr = warp >> 2, wc = warp & 3;
    const int Rb = wr * 32, Cb = wc * 32;

    float acc[2][4][4];
#pragma unroll
    for (int mt = 0; mt < 2; mt++)
#pragma unroll
        for (int nt = 0; nt < 4; nt++)
#pragma unroll
            for (int f = 0; f < 4; f++) acc[mt][nt][f] = 0.f;

#pragma unroll
    for (int k0 = 0; k0 < 128; k0 += 8) {
        unsigned a[2][4];
#pragma unroll
        for (int mt = 0; mt < 2; mt++) {
            int r = Rb + mt * 16 + g;
            a[mt][0] = sA[r * LDA + k0 + t];
            a[mt][1] = sA[(r + 8) * LDA + k0 + t];
            a[mt][2] = sA[r * LDA + k0 + t + 4];
            a[mt][3] = sA[(r + 8) * LDA + k0 + t + 4];
        }
#pragma unroll
        for (int nt = 0; nt < 4; nt++) {
            unsigned b0 = sW[(k0 + t) * LDW + Cb + nt * 8 + g];
            unsigned b1 = sW[(k0 + t + 4) * LDW + Cb + nt * 8 + g];
            mma8(acc[0][nt], a[0], b0, b1);
            mma8(acc[1][nt], a[1], b0, b1);
        }
    }

#pragma unroll
    for (int nt = 0; nt < 4; nt++) {
        int c0 = Cb + nt * 8 + 2 * t;
        float2 b2 = __ldg((const float2*)&bias[c0]);
#pragma unroll
        for (int mt = 0; mt < 2; mt++) {
            int r1 = row0 + Rb + mt * 16 + g;
            int r2 = r1 + 8;
            if (r1 < NN) {
                float2 o = make_float2(acc[mt][nt][0] + b2.x, acc[mt][nt][1] + b2.y);
                *(float2*)&out[(size_t)r1 * FF + c0] = o;
            }
            if (r2 < NN) {
                float2 o = make_float2(acc[mt][nt][2] + b2.x, acc[mt][nt][3] + b2.y);
                *(float2*)&out[(size_t)r2 * FF + c0] = o;
            }
        }
    }
}

// ---------------- Kernel 2: FUSED neighbor transform + attention -----------
// Persistent. Per tile: 8 nodes = 96 edges.
//   phase 1: MMA  T[96,128] = nbr_tile[96,64] @ Wn  (+bn), T kept in smem
//   phase 2: 8 groups x 32 lanes; group = node, lane covers 4 features.
// smem words: sT (aliases sA) 96*136, sWn 64*132, sA 96*68 (inside sT),
//             sq 8*128, sidx 96.
#define LDT 136
#define F_ST   0
#define F_SA   0                        /* aliased with sT */
#define F_SWN  (96 * LDT)               /* 13056 */
#define F_SQ   (F_SWN + 64 * LDW)       /* 21504 */
#define F_SIDX (F_SQ + 8 * FF)          /* 22528 */
#define F_TOTAL (F_SIDX + 96)           /* 22624 words */
#define FUSED_SMEM (F_TOTAL * 4)

__global__ __launch_bounds__(256, 2) void fused_attn(
    const float* __restrict__ nbr, const void* __restrict__ idxp,
    const float* __restrict__ Wn, const float* __restrict__ bn)
{
    extern __shared__ unsigned sh[];
    float*    sT   = (float*)(sh + F_ST);
    unsigned* sA   = sh + F_SA;
    unsigned* sWn  = sh + F_SWN;
    float*    sq   = (float*)(sh + F_SQ);
    int*      sidx = (int*)(sh + F_SIDX);

    const int tid = threadIdx.x;

    // stage Wn once (persistent)
    for (int e = tid; e < 64 * 32; e += 256) {
        int r = e >> 5, c4 = e & 31;
        float4 v = *(const float4*)&Wn[r * FF + c4 * 4];
        sWn[r * LDW + c4 * 4 + 0] = f2tf(v.x);
        sWn[r * LDW + c4 * 4 + 1] = f2tf(v.y);
        sWn[r * LDW + c4 * 4 + 2] = f2tf(v.z);
        sWn[r * LDW + c4 * 4 + 3] = f2tf(v.w);
    }
    const int is64 = g_is64;

    const int lane = tid & 31, g = lane >> 2, t = lane & 3;
    const int warp = tid >> 5, wr = warp >> 2, wc = warp & 3;  // wr in [0,2), wc in [0,4)
    const int Rb = wr * 48, Cb = wc * 32;

    // attention-phase mapping
    const int gn = tid >> 5;        // group (node within tile)
    const int j0 = (tid & 31) * 4;  // 4 consecutive features

    const int ntiles = NN / 8;      // 12500
    for (int tile = blockIdx.x; tile < ntiles; tile += gridDim.x) {
        const int n0 = tile * 8;

        __syncthreads();   // previous iteration's smem reads complete

        // ---- stage nbr (8 nodes x 12 x 64 contiguous) into sA (tf32) ----
        {
            const float* src = nbr + (size_t)n0 * (MM * NFF);
            for (int e = tid; e < 96 * 16; e += 256) {
                int r = e >> 4, c4 = e & 15;
                float4 v = *(const float4*)&src[r * NFF + c4 * 4];
                sA[r * LDA2 + c4 * 4 + 0] = f2tf(v.x);
                sA[r * LDA2 + c4 * 4 + 1] = f2tf(v.y);
                sA[r * LDA2 + c4 * 4 + 2] = f2tf(v.z);
                sA[r * LDA2 + c4 * 4 + 3] = f2tf(v.w);
            }
        }
        // ---- stage q rows (8 x 128) ----
        {
            float4 v = *(const float4*)&g_q[(size_t)n0 * FF + tid * 4];
            *(float4*)&sq[tid * 4] = v;
        }
        // ---- stage indices (96) ----
        if (tid < 96) {
            int ix;
            if (is64) ix = (int)((const long long*)idxp)[(size_t)n0 * MM + tid];
            else      ix = ((const int*)idxp)[(size_t)n0 * MM + tid];
            sidx[tid] = ix;
        }
        __syncthreads();

        // ---- MMA: T = sA(96x64) @ Wn(64x128) ----
        float acc[3][4][4];
#pragma unroll
        for (int mt = 0; mt < 3; mt++)
#pragma unroll
            for (int nt = 0; nt < 4; nt++)
#pragma unroll
                for (int f = 0; f < 4; f++) acc[mt][nt][f] = 0.f;

#pragma unroll
        for (int k0 = 0; k0 < 64; k0 += 8) {
            unsigned a[3][4];
#pragma unroll
            for (int mt = 0; mt < 3; mt++) {
                int r = Rb + mt * 16 + g;
                a[mt][0] = sA[r * LDA2 + k0 + t];
                a[mt][1] = sA[(r + 8) * LDA2 + k0 + t];
                a[mt][2] = sA[r * LDA2 + k0 + t + 4];
                a[mt][3] = sA[(r + 8) * LDA2 + k0 + t + 4];
            }
#pragma unroll
            for (int nt = 0; nt < 4; nt++) {
                unsigned b0 = sWn[(k0 + t) * LDW + Cb + nt * 8 + g];
                unsigned b1 = sWn[(k0 + t + 4) * LDW + Cb + nt * 8 + g];
                mma8(acc[0][nt], a[0], b0, b1);
                mma8(acc[1][nt], a[1], b0, b1);
                mma8(acc[2][nt], a[2], b0, b1);
            }
        }

        __syncthreads();   // all sA fragment reads done before sT overwrite

        // ---- write T (+bn) into sT ----
#pragma unroll
        for (int nt = 0; nt < 4; nt++) {
            int c0 = Cb + nt * 8 + 2 * t;
            float2 b2 = __ldg((const float2*)&bn[c0]);
#pragma unroll
            for (int mt = 0; mt < 3; mt++) {
                int r = Rb + mt * 16 + g;
                *(float2*)&sT[r * LDT + c0] =
                    make_float2(acc[mt][nt][0] + b2.x, acc[mt][nt][1] + b2.y);
                *(float2*)&sT[(r + 8) * LDT + c0] =
                    make_float2(acc[mt][nt][2] + b2.x, acc[mt][nt][3] + b2.y);
            }
        }
        __syncthreads();

        // ---- attention: group gn = node n0+gn, lane covers j0..j0+3 ----
        const float4 q4 = *(const float4*)&sq[gn * FF + j0];

        int ixs[MM];
#pragma unroll
        for (int m = 0; m < MM; m++) ixs[m] = sidx[gn * MM + m];

        float sc[MM];
#pragma unroll
        for (int m = 0; m < MM; m++) {
            const float4 k4 = *(const float4*)&g_k[(size_t)ixs[m] * FF + j0];
            const float4 T4 = *(const float4*)&sT[(gn * MM + m) * LDT + j0];
            float s = q4.x * (k4.x + T4.x);
            s = fmaf(q4.y, k4.y + T4.y, s);
            s = fmaf(q4.z, k4.z + T4.z, s);
            s = fmaf(q4.w, k4.w + T4.w, s);
            s += __shfl_xor_sync(0xffffffffu, s, 1);
            s += __shfl_xor_sync(0xffffffffu, s, 2);
            sc[m] = s * 0.25f;   // 1/sqrt(16)
        }
        float mx = sc[0];
#pragma unroll
        for (int m = 1; m < MM; m++) mx = fmaxf(mx, sc[m]);
        float se = 0.f;
#pragma unroll
        for (int m = 0; m < MM; m++) { sc[m] = __expf(sc[m] - mx); se += sc[m]; }
        const float inv = 1.f / se;

        float4 att = make_float4(0.f, 0.f, 0.f, 0.f);
#pragma unroll
        for (int m = 0; m < MM; m++) {
            const float w = sc[m] * inv;
            const float4 v4 = *(const float4*)&g_v[(size_t)ixs[m] * FF + j0];
            const float4 T4 = *(const float4*)&sT[(gn * MM + m) * LDT + j0];
            att.x = fmaf(w, v4.x + T4.x, att.x);
            att.y = fmaf(w, v4.y + T4.y, att.y);
            att.z = fmaf(w, v4.z + T4.z, att.z);
            att.w = fmaf(w, v4.w + T4.w, att.w);
        }
        *(float4*)&g_att[(size_t)(n0 + gn) * FF + j0] = att;
    }
}

// ---------------- Kernel 3: out GEMM + gate + LayerNorm (fused) ------------
__global__ __launch_bounds__(256, 2) void gemm_out(
    const float* __restrict__ atom,
    const float* __restrict__ Wo, const float* __restrict__ bo,
    const float* __restrict__ Wg, const float* __restrict__ bg,
    const float* __restrict__ gamma, const float* __restrict__ beta,
    float* __restrict__ outp)
{
    extern __shared__ unsigned sh[];
    unsigned* sA = sh;
    unsigned* sW = sh + 64 * LDA;
    float* zred = (float*)(sh + 64 * LDA + 128 * LDW);
    float* s1r  = zred + 256;
    float* s2r  = s1r + 256;

    const int tid  = threadIdx.x;
    const int row0 = blockIdx.x * 64;

    for (int e = tid; e < 64 * 32; e += 256) {
        int r = e >> 5, c4 = e & 31;
        int row = row0 + r;
        float4 v = (row < NN) ? *(const float4*)&g_att[(size_t)row * FF + c4 * 4]
                              : make_float4(0.f, 0.f, 0.f, 0.f);
        sA[r * LDA + c4 * 4 + 0] = f2tf(v.x);
        sA[r * LDA + c4 * 4 + 1] = f2tf(v.y);
        sA[r * LDA + c4 * 4 + 2] = f2tf(v.z);
        sA[r * LDA + c4 * 4 + 3] = f2tf(v.w);
    }
    for (int e = tid; e < 128 * 32; e += 256) {
        int r = e >> 5, c4 = e & 31;
        float4 v = *(const float4*)&Wo[r * FF + c4 * 4];
        sW[r * LDW + c4 * 4 + 0] = f2tf(v.x);
        sW[r * LDW + c4 * 4 + 1] = f2tf(v.y);
        sW[r * LDW + c4 * 4 + 2] = f2tf(v.z);
        sW[r * LDW + c4 * 4 + 3] = f2tf(v.w);
    }
    __syncthreads();

    const int lane = tid & 31, g = lane >> 2, t = lane & 3;
    const int warp = tid >> 5, wr = warp >> 2, wc = warp & 3;
    const int Rb = wr * 32, Cb = wc * 32;

    float acc[2][4][4];
#pragma unroll
    for (int mt = 0; mt < 2; mt++)
#pragma unroll
        for (int nt = 0; nt < 4; nt++)
#pragma unroll
            for (int f = 0; f < 4; f++) acc[mt][nt][f] = 0.f;

#pragma unroll
    for (int k0 = 0; k0 < 128; k0 += 8) {
        unsigned a[2][4];
#pragma unroll
        for (int mt = 0; mt < 2; mt++) {
            int r = Rb + mt * 16 + g;
            a[mt][0] = sA[r * LDA + k0 + t];
            a[mt][1] = sA[(r + 8) * LDA + k0 + t];
            a[mt][2] = sA[r * LDA + k0 + t + 4];
            a[mt][3] = sA[(r + 8) * LDA + k0 + t + 4];
        }
#pragma unroll
        for (int nt = 0; nt < 4; nt++) {
            unsigned b0 = sW[(k0 + t) * LDW + Cb + nt * 8 + g];
            unsigned b1 = sW[(k0 + t + 4) * LDW + Cb + nt * 8 + g];
            mma8(acc[0][nt], a[0], b0, b1);
            mma8(acc[1][nt], a[1], b0, b1);
        }
    }

    float res[2][4][4];
    float gp[2][2] = {{0.f, 0.f}, {0.f, 0.f}};
#pragma unroll
    for (int nt = 0; nt < 4; nt++) {
        int c0 = Cb + nt * 8 + 2 * t;
        float2 b2  = __ldg((const float2*)&bo[c0]);
        float2 wo2 = __ldg((const float2*)&Wg[c0]);
        float2 wr2 = __ldg((const float2*)&Wg[FF + c0]);
#pragma unroll
        for (int mt = 0; mt < 2; mt++) {
            int r1 = row0 + Rb + mt * 16 + g;
            int r2 = r1 + 8;
            float2 rA = (r1 < NN) ? *(const float2*)&atom[(size_t)r1 * FF + c0]
                                  : make_float2(0.f, 0.f);
            float2 rB = (r2 < NN) ? *(const float2*)&atom[(size_t)r2 * FF + c0]
                                  : make_float2(0.f, 0.f);
            acc[mt][nt][0] += b2.x; acc[mt][nt][1] += b2.y;
            acc[mt][nt][2] += b2.x; acc[mt][nt][3] += b2.y;
            res[mt][nt][0] = rA.x;  res[mt][nt][1] = rA.y;
            res[mt][nt][2] = rB.x;  res[mt][nt][3] = rB.y;
            gp[mt][0] += acc[mt][nt][0] * wo2.x + acc[mt][nt][1] * wo2.y
                       + rA.x * wr2.x + rA.y * wr2.y;
            gp[mt][1] += acc[mt][nt][2] * wo2.x + acc[mt][nt][3] * wo2.y
                       + rB.x * wr2.x + rB.y * wr2.y;
        }
    }
#pragma unroll
    for (int mt = 0; mt < 2; mt++) {
#pragma unroll
        for (int h = 0; h < 2; h++) {
            gp[mt][h] += __shfl_xor_sync(0xffffffffu, gp[mt][h], 1);
            gp[mt][h] += __shfl_xor_sync(0xffffffffu, gp[mt][h], 2);
        }
    }
    if (t == 0) {
#pragma unroll
        for (int mt = 0; mt < 2; mt++)
#pragma unroll
            for (int h = 0; h < 2; h++)
                zred[(Rb + mt * 16 + g + h * 8) * 4 + wc] = gp[mt][h];
    }
    __syncthreads();

    const float bgv = __ldg(bg);
    float gate[2][2];
#pragma unroll
    for (int mt = 0; mt < 2; mt++)
#pragma unroll
        for (int h = 0; h < 2; h++) {
            int rl = Rb + mt * 16 + g + h * 8;
            float z = zred[rl * 4 + 0] + zred[rl * 4 + 1] +
                      zred[rl * 4 + 2] + zred[rl * 4 + 3] + bgv;
            gate[mt][h] = 1.f / (1.f + __expf(-z));
        }

    float s1[2][2] = {{0.f, 0.f}, {0.f, 0.f}};
    float s2[2][2] = {{0.f, 0.f}, {0.f, 0.f}};
#pragma unroll
    for (int mt = 0; mt < 2; mt++)
#pragma unroll
        for (int nt = 0; nt < 4; nt++)
#pragma unroll
            for (int f = 0; f < 4; f++) {
                int h = f >> 1;
                float y = gate[mt][h] * acc[mt][nt][f]
                        + (1.f - gate[mt][h]) * res[mt][nt][f];
                res[mt][nt][f] = y;
                s1[mt][h] += y;
                s2[mt][h] += y * y;
            }
#pragma unroll
    for (int mt = 0; mt < 2; mt++)
#pragma unroll
        for (int h = 0; h < 2; h++) {
            s1[mt][h] += __shfl_xor_sync(0xffffffffu, s1[mt][h], 1);
            s1[mt][h] += __shfl_xor_sync(0xffffffffu, s1[mt][h], 2);
            s2[mt][h] += __shfl_xor_sync(0xffffffffu, s2[mt][h], 1);
            s2[mt][h] += __shfl_xor_sync(0xffffffffu, s2[mt][h], 2);
        }
    if (t == 0) {
#pragma unroll
        for (int mt = 0; mt < 2; mt++)
#pragma unroll
            for (int h = 0; h < 2; h++) {
                int rl = Rb + mt * 16 + g + h * 8;
                s1r[rl * 4 + wc] = s1[mt][h];
                s2r[rl * 4 + wc] = s2[mt][h];
            }
    }
    __syncthreads();

    float mu[2][2], rs[2][2];
#pragma unroll
    for (int mt = 0; mt < 2; mt++)
#pragma unroll
        for (int h = 0; h < 2; h++) {
            int rl = Rb + mt * 16 + g + h * 8;
            float m1 = (s1r[rl * 4 + 0] + s1r[rl * 4 + 1] +
                        s1r[rl * 4 + 2] + s1r[rl * 4 + 3]) * (1.f / FF);
            float m2 = (s2r[rl * 4 + 0] + s2r[rl * 4 + 1] +
                        s2r[rl * 4 + 2] + s2r[rl * 4 + 3]) * (1.f / FF);
            mu[mt][h] = m1;
            rs[mt][h] = rsqrtf(m2 - m1 * m1 + 1e-5f);
        }

#pragma unroll
    for (int nt = 0; nt < 4; nt++) {
        int c0 = Cb + nt * 8 + 2 * t;
        float2 ga2 = __ldg((const float2*)&gamma[c0]);
        float2 be2 = __ldg((const float2*)&beta[c0]);
#pragma unroll
        for (int mt = 0; mt < 2; mt++) {
            int r1 = row0 + Rb + mt * 16 + g;
            int r2 = r1 + 8;
            if (r1 < NN) {
                float2 o;
                o.x = (res[mt][nt][0] - mu[mt][0]) * rs[mt][0] * ga2.x + be2.x;
                o.y = (res[mt][nt][1] - mu[mt][0]) * rs[mt][0] * ga2.y + be2.y;
                *(float2*)&outp[(size_t)r1 * FF + c0] = o;
            }
            if (r2 < NN) {
                float2 o;
                o.x = (res[mt][nt][2] - mu[mt][1]) * rs[mt][1] * ga2.x + be2.x;
                o.y = (res[mt][nt][3] - mu[mt][1]) * rs[mt][1] * ga2.y + be2.y;
                *(float2*)&outp[(size_t)r2 * FF + c0] = o;
            }
        }
    }
}

// ---------------- launch ----------------------------------------------------
extern "C" void kernel_launch(void* const* d_in, const int* in_sizes, int n_in,
                              void* d_out, int out_size)
{
    const float* atom = (const float*)d_in[0];
    const float* nbrf = (const float*)d_in[1];
    const void*  idx  = d_in[2];
    const float* Wq = (const float*)d_in[3];
    const float* bq = (const float*)d_in[4];
    const float* Wk = (const float*)d_in[5];
    const float* bk = (const float*)d_in[6];
    const float* Wv = (const float*)d_in[7];
    const float* bv = (const float*)d_in[8];
    const float* Wn = (const float*)d_in[9];
    const float* bn = (const float*)d_in[10];
    const float* Wo = (const float*)d_in[11];
    const float* bo = (const float*)d_in[12];
    const float* Wg = (const float*)d_in[13];
    const float* bg = (const float*)d_in[14];
    const float* ga = (const float*)d_in[15];
    const float* be = (const float*)d_in[16];
    float* out = (float*)d_out;

    cudaFuncSetAttribute(gemm_qkv,  cudaFuncAttributeMaxDynamicSharedMemorySize, QKV_SMEM);
    cudaFuncSetAttribute(fused_attn, cudaFuncAttributeMaxDynamicSharedMemorySize, FUSED_SMEM);
    cudaFuncSetAttribute(gemm_out,  cudaFuncAttributeMaxDynamicSharedMemorySize, OUT_SMEM);

    detect_idx_kernel<<<1, 1>>>((const unsigned int*)idx);
    gemm_qkv<<<dim3((NN + 63) / 64, 3), 256, QKV_SMEM>>>(atom, Wq, bq, Wk, bk, Wv, bv);
    fused_attn<<<296, 256, FUSED_SMEM>>>(nbrf, idx, Wn, bn);
    gemm_out<<<(NN + 63) / 64, 256, OUT_SMEM>>>(atom, Wo, bo, Wg, bg, ga, be, out);
}